// round 2
// baseline (speedup 1.0000x reference)
#include <cuda_runtime.h>
#include <float.h>

// STCA loss. Chunked-scan formulation:
//  Phase 1: each (trace, chunk-of-512-timesteps) scanned by one thread,
//           coalesced via smem transpose staging; emits a 64B summary.
//  Phase 2: one thread per trace merges its 4 summaries (cluster monoid),
//           computes loss contribution + num_clusters; last block reduces.
// Output: d_out[0] = loss, d_out[1 + trace] = num_clusters as float.

#define B_DIM 128
#define N_DIM 256
#define T_DIM 2048
#define C_GAP 3
#define NTRACE (B_DIM * N_DIM)          // 32768

#define S_CHUNKS 4
#define CHUNK_T  (T_DIM / S_CHUNKS)     // 512
#define TPB      64                     // traces per block / threads per block
#define TT       32                     // timesteps per tile
#define TILES    (CHUNK_T / TT)         // 16
#define PITCH    36                     // smem row pitch (floats), conflict-free
#define GROUPS   (NTRACE / TPB)         // 512 trace-groups

#define P2_TPB   256
#define P2_BLOCKS (NTRACE / P2_TPB)     // 128

#define ICNT_INVALID (1 << 20)          // float-exact sentinel

// Per-(chunk,trace) summary: 4 x float4 = 64B.
//  [0] = {vmax, first_t, last_t, k}
//  [1] = {Fcnt, Fsum, Fpc, _}   first local cluster
//  [2] = {Icnt, Isum, Ipc, _}   best (smallest, earliest tie) interior cluster
//  [3] = {Lcnt, Lsum, Lpc, _}   last local cluster
__device__ float4       g_summ[S_CHUNKS * NTRACE * 4];
__device__ float        g_partial[P2_BLOCKS];
__device__ unsigned int g_count;        // zero-init; reset by reducing block

__global__ void __launch_bounds__(TPB)
stca_phase1(const float* __restrict__ vmem)
{
    __shared__ float sh[2][TPB][PITCH];

    const int tid       = threadIdx.x;
    const int traceBase = blockIdx.x * TPB;
    const int chunk     = blockIdx.y;

    // Cooperative coalesced loads: 8 lanes cover 128B contiguous per trace row.
    const int tq   = tid & 7;
    const int trl0 = tid >> 3;

    const float4* __restrict__ g4 = reinterpret_cast<const float4*>(vmem);
    const int chunkOff4 = chunk * (CHUNK_T / 4);   // float4 offset within trace

    float4 stage[8];
    #pragma unroll
    for (int k = 0; k < 8; k++) {
        const int tr = traceBase + trl0 + 8 * k;
        stage[k] = g4[tr * (T_DIM / 4) + chunkOff4 + tq];
    }

    // Scan state (local chunk)
    float vmax = -FLT_MAX;
    int   last = -1000000;          // local time of last spike
    int   k    = 0;                 // local cluster count
    int   ft   = -1, lt = -1;       // global first/last spike times
    int   curc = 0;   float cursum = 0.0f; int curpc = 0;
    int   Fcnt = 0;   float Fsum   = 0.0f; int Fpc   = 0;
    int   Icnt = ICNT_INVALID; float Isum = 0.0f; int Ipc = 0;

    const int gbase = chunk * CHUNK_T;

    #pragma unroll 1
    for (int tile = 0; tile < TILES; tile++) {
        const int buf = tile & 1;
        #pragma unroll
        for (int q = 0; q < 8; q++)
            *reinterpret_cast<float4*>(&sh[buf][trl0 + 8 * q][4 * tq]) = stage[q];
        __syncthreads();

        if (tile + 1 < TILES) {
            const int boff = chunkOff4 + (tile + 1) * (TT / 4) + tq;
            #pragma unroll
            for (int q = 0; q < 8; q++) {
                const int tr = traceBase + trl0 + 8 * q;
                stage[q] = g4[tr * (T_DIM / 4) + boff];
            }
        }

        const int tbase = tile * TT;
        #pragma unroll
        for (int j = 0; j < TT; j++) {
            const float v = sh[buf][tid][j];
            const int   t = tbase + j;
            vmax = fmaxf(vmax, v);
            if (v >= 0.0f) {                       // spike
                if (t - last > C_GAP) {            // new cluster
                    if (k == 1)      { Fcnt = curc; Fsum = cursum; Fpc = curpc; }
                    else if (k >= 2) { if (curc < Icnt) { Icnt = curc; Isum = cursum; Ipc = curpc; } }
                    k++;
                    curc = 0; cursum = 0.0f; curpc = 0;
                }
                curc++;
                if (v > 0.0f) { cursum += v; curpc++; }
                if (ft < 0) ft = gbase + t;
                lt = gbase + t;
                last = t;
            }
        }
    }

    if (k == 1) { Fcnt = curc; Fsum = cursum; Fpc = curpc; }
    // last open cluster = L (== cur); when k==1, F==L==cur.

    const int trace = traceBase + tid;
    const int idx   = (chunk * NTRACE + trace) * 4;
    g_summ[idx + 0] = make_float4(vmax, (float)ft, (float)lt, (float)k);
    g_summ[idx + 1] = make_float4((float)Fcnt, Fsum, (float)Fpc, 0.0f);
    g_summ[idx + 2] = make_float4((float)Icnt, Isum, (float)Ipc, 0.0f);
    g_summ[idx + 3] = make_float4((float)curc, cursum, (float)curpc, 0.0f);
}

__global__ void __launch_bounds__(P2_TPB)
stca_phase2(const int* __restrict__ labels, float* __restrict__ out)
{
    __shared__ float red[P2_TPB];
    __shared__ bool  amLast;

    const int tid   = threadIdx.x;
    const int trace = blockIdx.x * P2_TPB + tid;

    // Merge the S_CHUNKS summaries left-to-right (cluster monoid).
    float vmax = -FLT_MAX;
    int   last_t = -1000000;
    int   nclust = 0;
    int   opc = -1; float ops = 0.0f; int opp = 0;     // open cluster (opc<0: none)
    int   bc  = ICNT_INVALID; float bs = 0.0f; int bp = 0;  // best closed

    #pragma unroll
    for (int c = 0; c < S_CHUNKS; c++) {
        const int idx  = (c * NTRACE + trace) * 4;
        const float4 a = g_summ[idx + 0];
        const float4 f = g_summ[idx + 1];
        const float4 i = g_summ[idx + 2];
        const float4 l = g_summ[idx + 3];

        vmax = fmaxf(vmax, a.x);
        const int k = (int)a.w;
        if (k == 0) continue;
        const int ft = (int)a.y, lt = (int)a.z;
        const int Fcnt = (int)f.x, Fpc = (int)f.z;
        const int Icnt = (int)i.x, Ipc = (int)i.z;
        const int Lcnt = (int)l.x, Lpc = (int)l.z;

        if (opc >= 0 && (ft - last_t) <= C_GAP) {
            // chunk's first cluster merges with the open one
            const int   mc = opc + Fcnt;
            const float ms = ops + f.y;
            const int   mp = opp + Fpc;
            if (k == 1) {
                opc = mc; ops = ms; opp = mp;           // stays open
            } else {
                if (mc   < bc) { bc = mc;   bs = ms;  bp = mp;  }
                if (Icnt < bc) { bc = Icnt; bs = i.y; bp = Ipc; }
                opc = Lcnt; ops = l.y; opp = Lpc;
                nclust += k - 1;
            }
        } else {
            if (opc >= 0 && opc < bc) { bc = opc; bs = ops; bp = opp; }
            nclust += k;
            if (k == 1) {
                opc = Fcnt; ops = f.y; opp = Fpc;
            } else {
                if (Fcnt < bc) { bc = Fcnt; bs = f.y; bp = Fpc; }
                if (Icnt < bc) { bc = Icnt; bs = i.y; bp = Ipc; }
                opc = Lcnt; ops = l.y; opp = Lpc;
            }
        }
        last_t = lt;
    }
    if (opc >= 0 && opc < bc) { bc = opc; bs = ops; bp = opp; }

    out[1 + trace] = (float)nclust;

    const int b = trace / N_DIM;
    const int n = trace - b * N_DIM;
    float contrib = 0.0f;
    if (n == labels[b]) {
        if (nclust == 0) contrib = -vmax;                 // miss
    } else if (nclust > 0) {
        contrib = bs / fmaxf((float)bp, 1.0f);            // false positive
    }

    // Deterministic block tree reduction
    red[tid] = contrib;
    __syncthreads();
    #pragma unroll
    for (int off = P2_TPB / 2; off > 0; off >>= 1) {
        if (tid < off) red[tid] += red[tid + off];
        __syncthreads();
    }
    if (tid == 0) {
        g_partial[blockIdx.x] = red[0];
        __threadfence();
        const unsigned int v = atomicAdd(&g_count, 1u);
        amLast = (v == (unsigned)(gridDim.x - 1));
    }
    __syncthreads();

    if (amLast) {
        __threadfence();
        float x = (tid < P2_BLOCKS) ? g_partial[tid] : 0.0f;
        red[tid] = x;
        __syncthreads();
        #pragma unroll
        for (int off = P2_TPB / 2; off > 0; off >>= 1) {
            if (tid < off) red[tid] += red[tid + off];
            __syncthreads();
        }
        if (tid == 0) {
            out[0] = red[0];
            g_count = 0;           // reset for next graph replay
        }
    }
}

extern "C" void kernel_launch(void* const* d_in, const int* in_sizes, int n_in,
                              void* d_out, int out_size)
{
    const float* vmem   = (const float*)d_in[0];
    // d_in[1] (vlastmem) unused by the forward computation.
    const int*   labels = (const int*)d_in[2];
    float*       out    = (float*)d_out;

    dim3 grid1(GROUPS, S_CHUNKS);
    stca_phase1<<<grid1, TPB>>>(vmem);
    stca_phase2<<<P2_BLOCKS, P2_TPB>>>(labels, out);
}

// round 3
// speedup vs baseline: 1.1650x; 1.1650x over previous
#include <cuda_runtime.h>
#include <float.h>
#include <stdint.h>

// STCA loss — single fused kernel.
//  - 512 blocks x 256 threads. Block owns 64 traces; thread (c = tid>>6, tr = tid&63)
//    scans chunk c (512 timesteps) of trace tr, branch-free.
//  - Data staged gmem -> smem via cp.async double buffer (conflict-free LDS.128 scan).
//  - Chunk summaries merged in-block (cluster monoid), loss reduced via
//    deterministic trees + last-block pattern.
// Output: d_out[0] = loss, d_out[1 + trace] = num_clusters as float.

#define B_DIM 128
#define N_DIM 256
#define T_DIM 2048
#define C_GAP 3
#define NTRACE (B_DIM * N_DIM)        // 32768

#define S_CHUNKS 4
#define CHUNK_T  (T_DIM / S_CHUNKS)   // 512
#define TR_PB    64                   // traces per block
#define TPB      (TR_PB * S_CHUNKS)   // 256 threads
#define TT       32                   // timesteps per tile
#define NTILE    (CHUNK_T / TT)       // 16
#define PITCH    36                   // floats per row (conflict-free for LDS.128)
#define ROWS     TPB                  // 256 rows per tile (one per thread)
#define TILE_FLOATS (ROWS * PITCH)    // 9216
#define SMEM_BYTES  (2 * TILE_FLOATS * 4)   // 73728 B
#define NBLOCKS  (NTRACE / TR_PB)     // 512

#define SENT (1 << 30)                // sentinel, exact as float

__device__ float        g_partial[NBLOCKS];
__device__ unsigned int g_count;      // zero-init; reset each replay by last block

__device__ __forceinline__ void cp_async16(uint32_t saddr, const float* gptr) {
    asm volatile("cp.async.cg.shared.global [%0], [%1], 16;\n" :: "r"(saddr), "l"(gptr));
}
__device__ __forceinline__ void cp_commit() { asm volatile("cp.async.commit_group;\n"); }
template <int N>
__device__ __forceinline__ void cp_wait() { asm volatile("cp.async.wait_group %0;\n" :: "n"(N)); }

struct ScanState {
    float vmax;
    int   g;          // gap counter: t - last_spike (huge if none yet)
    int   k;          // clusters started
    int   ft;         // first spike t (local), -1 if none
    int   curc, curpc;   float cursum;    // open cluster
    int   Fc, Fp;        float Fs;        // first cluster
    int   Ic, Ip;        float Is;        // best interior cluster
};

__device__ __forceinline__ void step(ScanState& s, float v, int t) {
    s.vmax = fmaxf(s.vmax, v);
    const bool spike = (v >= 0.0f);
    const bool nw    = spike && (s.g > C_GAP);        // new cluster starts here
    const bool cF    = nw && (s.k == 1);              // close first cluster
    const bool cI    = nw && (s.k >= 2) && (s.curc < s.Ic);
    s.Fc = cF ? s.curc   : s.Fc;
    s.Fs = cF ? s.cursum : s.Fs;
    s.Fp = cF ? s.curpc  : s.Fp;
    s.Ic = cI ? s.curc   : s.Ic;
    s.Is = cI ? s.cursum : s.Is;
    s.Ip = cI ? s.curpc  : s.Ip;
    s.k += nw;
    const bool  pos = (v > 0.0f);
    const float va  = pos ? v : 0.0f;
    s.curc   = (nw ? 0 : s.curc)      + (int)spike;
    s.cursum = (nw ? 0.0f : s.cursum) + va;
    s.curpc  = (nw ? 0 : s.curpc)     + (int)pos;
    s.ft = (spike && s.ft < 0) ? t : s.ft;
    s.g  = spike ? 1 : (s.g + 1);
}

__global__ void __launch_bounds__(TPB)
stca_fused(const float* __restrict__ vmem,
           const int*   __restrict__ labels,
           float*       __restrict__ out)
{
    extern __shared__ float sm[];
    __shared__ bool amLast;

    const int tid       = threadIdx.x;
    const int traceBase = blockIdx.x * TR_PB;
    const int c         = tid >> 6;        // chunk 0..3
    const int tr        = tid & 63;        // trace-in-block

    // ---- cp.async load mapping: each thread fills 8 rows (row = tid>>3 + 32q), col tq ----
    const int tq   = tid & 7;              // float4 column 0..7
    const int row0 = tid >> 3;             // 0..31
    // gmem base for (row, tile): trace(row)*T + chunk(row)*CHUNK_T + tile*TT + tq*4
    const float* gbase[8];
    uint32_t     sbase[8];
    #pragma unroll
    for (int q = 0; q < 8; q++) {
        const int row = row0 + 32 * q;
        const int rtr = row & 63, rc = row >> 6;
        gbase[q] = vmem + (size_t)(traceBase + rtr) * T_DIM + rc * CHUNK_T + tq * 4;
        sbase[q] = (uint32_t)__cvta_generic_to_shared(sm) + (row * PITCH + tq * 4) * 4;
    }

    // prologue: tile 0 -> buf 0
    #pragma unroll
    for (int q = 0; q < 8; q++) cp_async16(sbase[q], gbase[q]);
    cp_commit();

    // ---- scan state ----
    ScanState s;
    s.vmax = -FLT_MAX; s.g = 1 << 20; s.k = 0; s.ft = -1;
    s.curc = 0; s.curpc = 0; s.cursum = 0.0f;
    s.Fc = 0; s.Fp = 0; s.Fs = 0.0f;
    s.Ic = SENT; s.Ip = 0; s.Is = 0.0f;

    const float* myrow[2];
    myrow[0] = sm + tid * PITCH;
    myrow[1] = sm + TILE_FLOATS + tid * PITCH;

    #pragma unroll 1
    for (int tile = 0; tile < NTILE; tile++) {
        const int buf = tile & 1;
        if (tile + 1 < NTILE) {
            const uint32_t soff = (buf ^ 1) * (TILE_FLOATS * 4);
            const int goff = (tile + 1) * TT;
            #pragma unroll
            for (int q = 0; q < 8; q++) cp_async16(sbase[q] + soff, gbase[q] + goff);
            cp_commit();
            cp_wait<1>();
        } else {
            cp_wait<0>();
        }
        __syncthreads();                       // tile data visible

        const int tb = tile * TT;
        const float* r = myrow[buf];
        #pragma unroll
        for (int j = 0; j < 8; j++) {
            const float4 v4 = *reinterpret_cast<const float4*>(r + 4 * j);
            const int t = tb + 4 * j;
            step(s, v4.x, t + 0);
            step(s, v4.y, t + 1);
            step(s, v4.z, t + 2);
            step(s, v4.w, t + 3);
        }
        __syncthreads();                       // done reading buf before overwrite
    }

    if (s.k == 1) { s.Fc = s.curc; s.Fs = s.cursum; s.Fp = s.curpc; }
    const int lt_loc = CHUNK_T - s.g;          // last spike (valid iff k>0)

    // ---- write summary to smem (reuse tile area; all threads past last barrier) ----
    __syncthreads();
    float* summ = sm;                          // [256][16]
    {
        float* w = summ + tid * 16;
        w[0]  = s.vmax;
        w[1]  = (float)(s.ft < 0 ? -1 : c * CHUNK_T + s.ft);
        w[2]  = (float)(c * CHUNK_T + lt_loc);
        w[3]  = (float)s.k;
        w[4]  = (float)s.Fc;  w[5]  = s.Fs;     w[6]  = (float)s.Fp;
        w[7]  = (float)s.Ic;  w[8]  = s.Is;     w[9]  = (float)s.Ip;
        w[10] = (float)s.curc; w[11] = s.cursum; w[12] = (float)s.curpc;
    }
    __syncthreads();

    // ---- merge 4 chunk summaries per trace (threads 0..63) ----
    float* red = sm + TPB * 16;                // [256]
    float contrib = 0.0f;
    if (tid < TR_PB) {
        float vmax = -FLT_MAX;
        int last_t = -1000000, nclust = 0;
        int   opc = -1, opp = 0;  float ops = 0.0f;          // open cluster
        int   bc = SENT, bp = 0;  float bs = 0.0f;           // best closed
        #pragma unroll
        for (int cc = 0; cc < S_CHUNKS; cc++) {
            const float* w = summ + (cc * TR_PB + tid) * 16;
            vmax = fmaxf(vmax, w[0]);
            const int k = (int)w[3];
            if (k == 0) continue;
            const int ft = (int)w[1], lt = (int)w[2];
            const int Fc = (int)w[4], Fp = (int)w[6];
            const int Ic = (int)w[7], Ip = (int)w[9];
            const int Lc = (int)w[10], Lp = (int)w[12];
            const float Fs = w[5], Is = w[8], Ls = w[11];

            if (opc >= 0 && (ft - last_t) <= C_GAP) {
                const int   mc = opc + Fc;
                const float ms = ops + Fs;
                const int   mp = opp + Fp;
                if (k == 1) { opc = mc; ops = ms; opp = mp; }
                else {
                    if (mc < bc) { bc = mc; bs = ms; bp = mp; }
                    if (Ic < bc) { bc = Ic; bs = Is; bp = Ip; }
                    opc = Lc; ops = Ls; opp = Lp;
                    nclust += k - 1;
                }
            } else {
                if (opc >= 0 && opc < bc) { bc = opc; bs = ops; bp = opp; }
                nclust += k;
                if (k == 1) { opc = Fc; ops = Fs; opp = Fp; }
                else {
                    if (Fc < bc) { bc = Fc; bs = Fs; bp = Fp; }
                    if (Ic < bc) { bc = Ic; bs = Is; bp = Ip; }
                    opc = Lc; ops = Ls; opp = Lp;
                }
            }
            last_t = lt;
        }
        if (opc >= 0 && opc < bc) { bc = opc; bs = ops; bp = opp; }

        const int trace = traceBase + tid;
        out[1 + trace] = (float)nclust;

        const int b = trace / N_DIM;
        const int n = trace - b * N_DIM;
        if (n == labels[b]) {
            if (nclust == 0) contrib = -vmax;
        } else if (nclust > 0) {
            contrib = bs / fmaxf((float)bp, 1.0f);
        }
    }

    // ---- block tree reduction over 64 contributions ----
    red[tid] = contrib;                        // threads >=64 contribute 0
    __syncthreads();
    #pragma unroll
    for (int off = TPB / 2; off > 0; off >>= 1) {
        if (tid < off) red[tid] += red[tid + off];
        __syncthreads();
    }
    if (tid == 0) {
        g_partial[blockIdx.x] = red[0];
        __threadfence();
        amLast = (atomicAdd(&g_count, 1u) == (unsigned)(gridDim.x - 1));
    }
    __syncthreads();

    if (amLast) {
        __threadfence();
        red[tid] = g_partial[tid] + g_partial[tid + TPB];   // 512 partials, 256 threads
        __syncthreads();
        #pragma unroll
        for (int off = TPB / 2; off > 0; off >>= 1) {
            if (tid < off) red[tid] += red[tid + off];
            __syncthreads();
        }
        if (tid == 0) {
            out[0] = red[0];
            g_count = 0;                       // reset for next graph replay
        }
    }
}

extern "C" void kernel_launch(void* const* d_in, const int* in_sizes, int n_in,
                              void* d_out, int out_size)
{
    const float* vmem   = (const float*)d_in[0];
    // d_in[1] (vlastmem) unused by the forward computation.
    const int*   labels = (const int*)d_in[2];
    float*       out    = (float*)d_out;

    cudaFuncSetAttribute(stca_fused, cudaFuncAttributeMaxDynamicSharedMemorySize, SMEM_BYTES);
    stca_fused<<<NBLOCKS, TPB, SMEM_BYTES>>>(vmem, labels, out);
}

// round 4
// speedup vs baseline: 1.8097x; 1.5534x over previous
#include <cuda_runtime.h>
#include <float.h>
#include <stdint.h>

// STCA loss — fused kernel, bitmask spike scan.
//  1024 blocks x 128 threads. Block owns 32 traces; thread (c = tid>>5, tr = tid&31)
//  scans chunk c (512 timesteps) of trace tr.
//  Per 32-step word: build spike mask from sign bits, then iterate ONLY set bits
//  (~7% density) running the cluster monoid. vmax tracked unconditionally (cheap).
//  Data staged gmem->smem via cp.async double buffer (conflict-free LDS.128).
//  Chunk summaries merged in-block; loss via deterministic trees + last-block.
// Output: d_out[0] = loss, d_out[1 + trace] = num_clusters as float.

#define B_DIM 128
#define N_DIM 256
#define T_DIM 2048
#define C_GAP 3
#define NTRACE (B_DIM * N_DIM)        // 32768

#define S_CHUNKS 4
#define CHUNK_T  (T_DIM / S_CHUNKS)   // 512
#define TR_PB    32                   // traces per block
#define TPB      (TR_PB * S_CHUNKS)   // 128 threads
#define TT       32                   // timesteps per tile (= one mask word)
#define NTILE    (CHUNK_T / TT)       // 16
#define PITCH    36                   // floats per smem row (conflict-free LDS.128)
#define TILE_FLOATS (TPB * PITCH)     // 4608
#define SMEM_BYTES  (2 * TILE_FLOATS * 4)   // 36864 B -> 6 blocks/SM
#define NBLOCKS  (NTRACE / TR_PB)     // 1024

#define SENT (1 << 30)

__device__ float        g_partial[NBLOCKS];
__device__ unsigned int g_count;      // zero-init; reset each replay by last block

__device__ __forceinline__ void cp_async16(uint32_t saddr, const float* gptr) {
    asm volatile("cp.async.cg.shared.global [%0], [%1], 16;\n" :: "r"(saddr), "l"(gptr));
}
__device__ __forceinline__ void cp_commit() { asm volatile("cp.async.commit_group;\n"); }
template <int N>
__device__ __forceinline__ void cp_wait() { asm volatile("cp.async.wait_group %0;\n" :: "n"(N)); }

__global__ void __launch_bounds__(TPB)
stca_fused(const float* __restrict__ vmem,
           const int*   __restrict__ labels,
           float*       __restrict__ out)
{
    extern __shared__ float sm[];
    __shared__ bool amLast;

    const int tid       = threadIdx.x;
    const int traceBase = blockIdx.x * TR_PB;
    const int c         = tid >> 5;       // chunk 0..3
    // thread's own data row = tid (trace tid&31, chunk tid>>5)

    // ---- cp.async mapping: 128 rows x 8 float4 per tile; thread fills 8 rows ----
    const int tq   = tid & 7;             // float4 column 0..7
    const int row0 = tid >> 3;            // 0..15
    const float* gbase[8];
    uint32_t     sbase[8];
    #pragma unroll
    for (int q = 0; q < 8; q++) {
        const int r   = row0 + 16 * q;
        const int rtr = r & 31, rc = r >> 5;
        gbase[q] = vmem + (size_t)(traceBase + rtr) * T_DIM + rc * CHUNK_T + tq * 4;
        sbase[q] = (uint32_t)__cvta_generic_to_shared(sm) + (r * PITCH + tq * 4) * 4;
    }

    #pragma unroll
    for (int q = 0; q < 8; q++) cp_async16(sbase[q], gbase[q]);   // tile 0 -> buf 0
    cp_commit();

    // ---- scan state ----
    float vmax = -FLT_MAX;
    int   last = -1000000;                // chunk-local time of previous spike
    int   k = 0, ft = -1;
    int   curc = 0, curpc = 0;  float cursum = 0.0f;
    int   Fc = 0,   Fp = 0;     float Fs = 0.0f;
    int   Ic = SENT, Ip = 0;    float Is = 0.0f;

    #pragma unroll 1
    for (int tile = 0; tile < NTILE; tile++) {
        const int buf = tile & 1;
        if (tile + 1 < NTILE) {
            const uint32_t soff = (buf ^ 1) * (TILE_FLOATS * 4);
            const int goff = (tile + 1) * TT;
            #pragma unroll
            for (int q = 0; q < 8; q++) cp_async16(sbase[q] + soff, gbase[q] + goff);
            cp_commit();
            cp_wait<1>();
        } else {
            cp_wait<0>();
        }
        __syncthreads();

        const float* r = sm + buf * TILE_FLOATS + tid * PITCH;

        // Build spike mask (bit j = v[j] >= 0) + vmax, 32 steps.
        uint32_t nm = 0;                  // negative-sign mask
        float vm = vmax;
        #pragma unroll
        for (int q = 0; q < 8; q++) {
            const float4 v = *reinterpret_cast<const float4*>(r + 4 * q);
            vm = fmaxf(vm, fmaxf(fmaxf(v.x, v.y), fmaxf(v.z, v.w)));
            const uint32_t nib = (__float_as_uint(v.x) >> 31)
                               | ((__float_as_uint(v.y) >> 31) << 1)
                               | ((__float_as_uint(v.z) >> 31) << 2)
                               | ((__float_as_uint(v.w) >> 31) << 3);
            nm |= nib << (4 * q);
        }
        vmax = vm;
        uint32_t m = ~nm;                 // spike mask

        if (m) {
            const int wb = tile * TT;
            if (ft < 0) ft = wb + __ffs(m) - 1;
            do {
                const int i = __ffs(m) - 1;
                m &= m - 1;
                const float v = r[i];     // v >= 0 guaranteed
                const int  tg = wb + i;
                const bool nw = (tg - last) > C_GAP;
                const bool cF = nw && (k == 1);
                const bool cI = nw && (k >= 2) && (curc < Ic);
                Fc = cF ? curc : Fc;  Fs = cF ? cursum : Fs;  Fp = cF ? curpc : Fp;
                Ic = cI ? curc : Ic;  Is = cI ? cursum : Is;  Ip = cI ? curpc : Ip;
                k += nw;
                curc   = (nw ? 0 : curc) + 1;
                cursum = (nw ? 0.0f : cursum) + v;              // v==0 adds 0 (exact)
                curpc  = (nw ? 0 : curpc) + (v > 0.0f ? 1 : 0);
                last = tg;
            } while (m);
        }
        __syncthreads();                  // done reading buf before overwrite
    }

    if (k == 1) { Fc = curc; Fs = cursum; Fp = curpc; }
    // open/last cluster L = cur; lt = last (valid iff k>0)

    // ---- chunk summaries to smem: [128][16] ----
    __syncthreads();
    float* summ = sm;
    {
        float* w = summ + tid * 16;
        w[0]  = vmax;
        w[1]  = (float)(ft < 0 ? -1 : c * CHUNK_T + ft);
        w[2]  = (float)(c * CHUNK_T + last);
        w[3]  = (float)k;
        w[4]  = (float)Fc;   w[5]  = Fs;     w[6]  = (float)Fp;
        w[7]  = (float)Ic;   w[8]  = Is;     w[9]  = (float)Ip;
        w[10] = (float)curc; w[11] = cursum; w[12] = (float)curpc;
    }
    __syncthreads();

    // ---- merge 4 chunk summaries per trace (threads 0..31) ----
    float* red = sm + TPB * 16;
    float contrib = 0.0f;
    if (tid < TR_PB) {
        float vx = -FLT_MAX;
        int last_t = -1000000, nclust = 0;
        int   opc = -1, opp = 0;  float ops = 0.0f;            // open cluster
        int   bc = SENT, bp = 0;  float bs = 0.0f;             // best closed
        #pragma unroll
        for (int cc = 0; cc < S_CHUNKS; cc++) {
            const float* w = summ + (cc * TR_PB + tid) * 16;
            vx = fmaxf(vx, w[0]);
            const int kk = (int)w[3];
            if (kk == 0) continue;
            const int ftc = (int)w[1], ltc = (int)w[2];
            const int fC = (int)w[4], fP = (int)w[6];
            const int iC = (int)w[7], iP = (int)w[9];
            const int lC = (int)w[10], lP = (int)w[12];
            const float fS = w[5], iS = w[8], lS = w[11];

            if (opc >= 0 && (ftc - last_t) <= C_GAP) {
                const int   mc = opc + fC;
                const float ms = ops + fS;
                const int   mp = opp + fP;
                if (kk == 1) { opc = mc; ops = ms; opp = mp; }
                else {
                    if (mc < bc) { bc = mc; bs = ms; bp = mp; }
                    if (iC < bc) { bc = iC; bs = iS; bp = iP; }
                    opc = lC; ops = lS; opp = lP;
                    nclust += kk - 1;
                }
            } else {
                if (opc >= 0 && opc < bc) { bc = opc; bs = ops; bp = opp; }
                nclust += kk;
                if (kk == 1) { opc = fC; ops = fS; opp = fP; }
                else {
                    if (fC < bc) { bc = fC; bs = fS; bp = fP; }
                    if (iC < bc) { bc = iC; bs = iS; bp = iP; }
                    opc = lC; ops = lS; opp = lP;
                }
            }
            last_t = ltc;
        }
        if (opc >= 0 && opc < bc) { bc = opc; bs = ops; bp = opp; }

        const int trace = traceBase + tid;
        out[1 + trace] = (float)nclust;

        const int b = trace / N_DIM;
        const int n = trace - b * N_DIM;
        if (n == labels[b]) {
            if (nclust == 0) contrib = -vx;
        } else if (nclust > 0) {
            contrib = bs / fmaxf((float)bp, 1.0f);
        }
    }

    // ---- block tree reduction (128 threads; >=32 contribute 0) ----
    red[tid] = contrib;
    __syncthreads();
    #pragma unroll
    for (int off = TPB / 2; off > 0; off >>= 1) {
        if (tid < off) red[tid] += red[tid + off];
        __syncthreads();
    }
    if (tid == 0) {
        g_partial[blockIdx.x] = red[0];
        __threadfence();
        amLast = (atomicAdd(&g_count, 1u) == (unsigned)(gridDim.x - 1));
    }
    __syncthreads();

    if (amLast) {
        __threadfence();
        float x = 0.0f;
        #pragma unroll
        for (int j = 0; j < NBLOCKS / TPB; j++) x += g_partial[tid + TPB * j];
        red[tid] = x;
        __syncthreads();
        #pragma unroll
        for (int off = TPB / 2; off > 0; off >>= 1) {
            if (tid < off) red[tid] += red[tid + off];
            __syncthreads();
        }
        if (tid == 0) {
            out[0] = red[0];
            g_count = 0;                  // reset for next graph replay
        }
    }
}

extern "C" void kernel_launch(void* const* d_in, const int* in_sizes, int n_in,
                              void* d_out, int out_size)
{
    const float* vmem   = (const float*)d_in[0];
    // d_in[1] (vlastmem) unused by the forward computation.
    const int*   labels = (const int*)d_in[2];
    float*       out    = (float*)d_out;

    stca_fused<<<NBLOCKS, TPB, SMEM_BYTES>>>(vmem, labels, out);
}

// round 6
// speedup vs baseline: 1.8895x; 1.0441x over previous
#include <cuda_runtime.h>
#include <float.h>
#include <stdint.h>

// STCA loss — fused kernel, bitmask spike scan, warp-autonomous staging.
//  1024 blocks x 128 threads. Block owns 32 traces; thread (c = tid>>5, tr = tid&31)
//  scans chunk c (512 timesteps) of trace tr.
//  Each WARP stages its own 32 rows (gmem->smem, cp.async double buffer) and syncs
//  only with __syncwarp — no block barriers in the hot loop.
//  FIX vs r5: final tile must cp.async.wait_group 0 (only one group in flight).
// Output: d_out[0] = loss, d_out[1 + trace] = num_clusters as float.

#define B_DIM 128
#define N_DIM 256
#define T_DIM 2048
#define C_GAP 3
#define NTRACE (B_DIM * N_DIM)        // 32768

#define S_CHUNKS 4
#define CHUNK_T  (T_DIM / S_CHUNKS)   // 512
#define TR_PB    32                   // traces per block
#define TPB      (TR_PB * S_CHUNKS)   // 128 threads
#define TT       32                   // timesteps per tile (= one mask word)
#define NTILE    (CHUNK_T / TT)       // 16
#define PITCH    36                   // floats per smem row (conflict-free LDS.128)
#define TILE_FLOATS (TPB * PITCH)     // 4608 (per buffer, whole block)
#define SMEM_BYTES  (2 * TILE_FLOATS * 4)   // 36864 B -> 6 blocks/SM
#define NBLOCKS  (NTRACE / TR_PB)     // 1024

#define SENT (1 << 30)

__device__ float        g_partial[NBLOCKS];
__device__ unsigned int g_count;      // zero-init; reset each replay by last block

__device__ __forceinline__ void cp_async16(uint32_t saddr, const float* gptr) {
    asm volatile("cp.async.cg.shared.global [%0], [%1], 16;\n" :: "r"(saddr), "l"(gptr));
}
__device__ __forceinline__ void cp_commit() { asm volatile("cp.async.commit_group;\n"); }
template <int N>
__device__ __forceinline__ void cp_wait() { asm volatile("cp.async.wait_group %0;\n" :: "n"(N)); }

__global__ void __launch_bounds__(TPB)
stca_fused(const float* __restrict__ vmem,
           const int*   __restrict__ labels,
           float*       __restrict__ out)
{
    extern __shared__ float sm[];
    __shared__ bool amLast;

    const int tid       = threadIdx.x;
    const int traceBase = blockIdx.x * TR_PB;
    const int c         = tid >> 5;       // chunk 0..3 (row = tid: trace tid&31, chunk tid>>5)
    const int wid       = tid >> 5;       // warp id (rows 32w..32w+31 belong to warp w)
    const int lane      = tid & 31;

    // ---- warp-local cp.async mapping: warp w stages rows 32w..32w+31 ----
    const int tq  = lane & 7;             // float4 column 0..7
    const int rl0 = lane >> 3;            // 0..3
    const float* gbase[8];
    uint32_t     sbase[8];
    #pragma unroll
    for (int q = 0; q < 8; q++) {
        const int r   = 32 * wid + rl0 + 4 * q;     // block-local row (within this warp's 32)
        const int rtr = r & 31, rc = r >> 5;
        gbase[q] = vmem + (size_t)(traceBase + rtr) * T_DIM + rc * CHUNK_T + tq * 4;
        sbase[q] = (uint32_t)__cvta_generic_to_shared(sm) + (r * PITCH + tq * 4) * 4;
    }

    // prologue: tiles 0 and 1 in flight
    #pragma unroll
    for (int q = 0; q < 8; q++) cp_async16(sbase[q], gbase[q]);
    cp_commit();
    #pragma unroll
    for (int q = 0; q < 8; q++) cp_async16(sbase[q] + TILE_FLOATS * 4, gbase[q] + TT);
    cp_commit();

    // ---- scan state ----
    float vmax = -FLT_MAX;
    int   last = -1000000;                // chunk-local time of previous spike
    int   k = 0, ft = -1;
    int   curc = 0, curpc = 0;  float cursum = 0.0f;
    int   Fc = 0,   Fp = 0;     float Fs = 0.0f;
    int   Ic = SENT, Ip = 0;    float Is = 0.0f;

    const float* myrow0 = sm + tid * PITCH;

    #pragma unroll 1
    for (int tile = 0; tile < NTILE; tile++) {
        const int buf = tile & 1;
        // Last tile has only ONE group in flight -> must drain fully (r5 bug).
        if (tile == NTILE - 1) cp_wait<0>(); else cp_wait<1>();
        __syncwarp();                     // producer lanes' smem writes visible warp-wide

        const float* r = myrow0 + buf * TILE_FLOATS;

        // Build spike mask (bit j = v[j] >= 0) + vmax over 32 steps.
        uint32_t nm = 0;
        float vm = vmax;
        #pragma unroll
        for (int q = 0; q < 8; q++) {
            const float4 v = *reinterpret_cast<const float4*>(r + 4 * q);
            vm = fmaxf(vm, fmaxf(fmaxf(v.x, v.y), fmaxf(v.z, v.w)));
            const uint32_t nib = (__float_as_uint(v.x) >> 31)
                               | ((__float_as_uint(v.y) >> 31) << 1)
                               | ((__float_as_uint(v.z) >> 31) << 2)
                               | ((__float_as_uint(v.w) >> 31) << 3);
            nm |= nib << (4 * q);
        }
        vmax = vm;
        uint32_t m = ~nm;                 // spike mask

        if (m) {
            const int wb = tile * TT;
            if (ft < 0) ft = wb + __ffs(m) - 1;
            do {
                const int i = __ffs(m) - 1;
                m &= m - 1;
                const float v = r[i];     // v >= 0 guaranteed
                const int  tg = wb + i;
                const bool nw = (tg - last) > C_GAP;
                const bool cF = nw && (k == 1);
                const bool cI = nw && (k >= 2) && (curc < Ic);
                Fc = cF ? curc : Fc;  Fs = cF ? cursum : Fs;  Fp = cF ? curpc : Fp;
                Ic = cI ? curc : Ic;  Is = cI ? cursum : Is;  Ip = cI ? curpc : Ip;
                k += nw;
                curc   = (nw ? 0 : curc) + 1;
                cursum = (nw ? 0.0f : cursum) + v;
                curpc  = (nw ? 0 : curpc) + (v > 0.0f ? 1 : 0);
                last = tg;
            } while (m);
        }

        __syncwarp();                     // all lanes done reading buf
        if (tile + 2 < NTILE) {           // refill buf with tile+2
            const uint32_t soff = buf * (TILE_FLOATS * 4);
            const int goff = (tile + 2) * TT;
            #pragma unroll
            for (int q = 0; q < 8; q++) cp_async16(sbase[q] + soff, gbase[q] + goff);
            cp_commit();
        }
    }

    if (k == 1) { Fc = curc; Fs = cursum; Fp = curpc; }

    // ---- chunk summaries to smem: [128][16] (single block barrier first) ----
    __syncthreads();
    float* summ = sm;
    {
        float* w = summ + tid * 16;
        w[0]  = vmax;
        w[1]  = (float)(ft < 0 ? -1 : c * CHUNK_T + ft);
        w[2]  = (float)(c * CHUNK_T + last);
        w[3]  = (float)k;
        w[4]  = (float)Fc;   w[5]  = Fs;     w[6]  = (float)Fp;
        w[7]  = (float)Ic;   w[8]  = Is;     w[9]  = (float)Ip;
        w[10] = (float)curc; w[11] = cursum; w[12] = (float)curpc;
    }
    __syncthreads();

    // ---- merge 4 chunk summaries per trace (threads 0..31) ----
    float* red = sm + TPB * 16;
    float contrib = 0.0f;
    if (tid < TR_PB) {
        float vx = -FLT_MAX;
        int last_t = -1000000, nclust = 0;
        int   opc = -1, opp = 0;  float ops = 0.0f;            // open cluster
        int   bc = SENT, bp = 0;  float bs = 0.0f;             // best closed
        #pragma unroll
        for (int cc = 0; cc < S_CHUNKS; cc++) {
            const float* w = summ + (cc * TR_PB + tid) * 16;
            vx = fmaxf(vx, w[0]);
            const int kk = (int)w[3];
            if (kk == 0) continue;
            const int ftc = (int)w[1], ltc = (int)w[2];
            const int fC = (int)w[4], fP = (int)w[6];
            const int iC = (int)w[7], iP = (int)w[9];
            const int lC = (int)w[10], lP = (int)w[12];
            const float fS = w[5], iS = w[8], lS = w[11];

            if (opc >= 0 && (ftc - last_t) <= C_GAP) {
                const int   mc = opc + fC;
                const float ms = ops + fS;
                const int   mp = opp + fP;
                if (kk == 1) { opc = mc; ops = ms; opp = mp; }
                else {
                    if (mc < bc) { bc = mc; bs = ms; bp = mp; }
                    if (iC < bc) { bc = iC; bs = iS; bp = iP; }
                    opc = lC; ops = lS; opp = lP;
                    nclust += kk - 1;
                }
            } else {
                if (opc >= 0 && opc < bc) { bc = opc; bs = ops; bp = opp; }
                nclust += kk;
                if (kk == 1) { opc = fC; ops = fS; opp = fP; }
                else {
                    if (fC < bc) { bc = fC; bs = fS; bp = fP; }
                    if (iC < bc) { bc = iC; bs = iS; bp = iP; }
                    opc = lC; ops = lS; opp = lP;
                }
            }
            last_t = ltc;
        }
        if (opc >= 0 && opc < bc) { bc = opc; bs = ops; bp = opp; }

        const int trace = traceBase + tid;
        out[1 + trace] = (float)nclust;

        const int b = trace / N_DIM;
        const int n = trace - b * N_DIM;
        if (n == labels[b]) {
            if (nclust == 0) contrib = -vx;
        } else if (nclust > 0) {
            contrib = bs / fmaxf((float)bp, 1.0f);
        }
    }

    // ---- block tree reduction (128 threads; >=32 contribute 0) ----
    red[tid] = contrib;
    __syncthreads();
    #pragma unroll
    for (int off = TPB / 2; off > 0; off >>= 1) {
        if (tid < off) red[tid] += red[tid + off];
        __syncthreads();
    }
    if (tid == 0) {
        g_partial[blockIdx.x] = red[0];
        __threadfence();
        amLast = (atomicAdd(&g_count, 1u) == (unsigned)(gridDim.x - 1));
    }
    __syncthreads();

    if (amLast) {
        __threadfence();
        float x = 0.0f;
        #pragma unroll
        for (int j = 0; j < NBLOCKS / TPB; j++) x += g_partial[tid + TPB * j];
        red[tid] = x;
        __syncthreads();
        #pragma unroll
        for (int off = TPB / 2; off > 0; off >>= 1) {
            if (tid < off) red[tid] += red[tid + off];
            __syncthreads();
        }
        if (tid == 0) {
            out[0] = red[0];
            g_count = 0;                  // reset for next graph replay
        }
    }
}

extern "C" void kernel_launch(void* const* d_in, const int* in_sizes, int n_in,
                              void* d_out, int out_size)
{
    const float* vmem   = (const float*)d_in[0];
    // d_in[1] (vlastmem) unused by the forward computation.
    const int*   labels = (const int*)d_in[2];
    float*       out    = (float*)d_out;

    stca_fused<<<NBLOCKS, TPB, SMEM_BYTES>>>(vmem, labels, out);
}

// round 7
// speedup vs baseline: 2.3202x; 1.2280x over previous
#include <cuda_runtime.h>
#include <float.h>
#include <stdint.h>

// STCA loss — fused kernel, bitmask spike scan, warp-autonomous 3-stage cp.async ring.
//  1024 blocks x 128 threads, all resident in ONE wave (smem 30.7KB -> 7 blocks/SM).
//  Block owns 32 traces; thread (c = tid>>5, tr = tid&31) scans chunk c (512 steps).
//  Warp w stages rows 32w..32w+31 itself; __syncwarp only in the hot loop.
//  Per 16-step tile: sign mask via PRMT + magic multiply, iterate set bits (~7%).
//  vmax computed LAZILY (gmem rescan) only for spikeless chunks (P ~ 4e-16).
// Output: d_out[0] = loss, d_out[1 + trace] = num_clusters as float.

#define B_DIM 128
#define N_DIM 256
#define T_DIM 2048
#define C_GAP 3
#define NTRACE (B_DIM * N_DIM)        // 32768

#define S_CHUNKS 4
#define CHUNK_T  (T_DIM / S_CHUNKS)   // 512
#define TR_PB    32                   // traces per block
#define TPB      (TR_PB * S_CHUNKS)   // 128 threads
#define TT       16                   // timesteps per tile
#define NTILE    (CHUNK_T / TT)       // 32
#define PITCH    20                   // floats per smem row (80B stride, LDS.128 conflict-free)
#define TILE_FLOATS (TPB * PITCH)     // 2560
#define TILE_BYTES  (TILE_FLOATS * 4) // 10240
#define NBUF     3
#define NBLOCKS  (NTRACE / TR_PB)     // 1024

#define SENT (1 << 30)

__device__ float        g_partial[NBLOCKS];
__device__ unsigned int g_count;      // zero-init; reset each replay by last block

__device__ __forceinline__ void cp_async16(uint32_t saddr, const float* gptr) {
    asm volatile("cp.async.cg.shared.global [%0], [%1], 16;\n" :: "r"(saddr), "l"(gptr));
}
__device__ __forceinline__ void cp_commit() { asm volatile("cp.async.commit_group;\n"); }
template <int N>
__device__ __forceinline__ void cp_wait() { asm volatile("cp.async.wait_group %0;\n" :: "n"(N)); }

__global__ void __launch_bounds__(TPB)
stca_fused(const float* __restrict__ vmem,
           const int*   __restrict__ labels,
           float*       __restrict__ out)
{
    __shared__ float sm[NBUF * TILE_FLOATS];
    __shared__ bool  amLast;

    const int tid       = threadIdx.x;
    const int traceBase = blockIdx.x * TR_PB;
    const int c         = tid >> 5;       // chunk 0..3 (= warp id; row = tid)
    const int wid       = tid >> 5;
    const int lane      = tid & 31;

    // ---- warp-local cp.async mapping: warp w stages rows 32w..32w+31 ----
    // Per tile a row is 16 floats = 4 float4. lane: tq = lane&3, rl0 = lane>>2 (0..7), q 0..3.
    const int tq  = lane & 3;
    const int rl0 = lane >> 2;
    const float* gbase[4];
    uint32_t     sbase[4];
    #pragma unroll
    for (int q = 0; q < 4; q++) {
        const int r   = 32 * wid + rl0 + 8 * q;     // block-local row
        const int rtr = r & 31, rc = r >> 5;
        gbase[q] = vmem + (size_t)(traceBase + rtr) * T_DIM + rc * CHUNK_T + tq * 4;
        sbase[q] = (uint32_t)__cvta_generic_to_shared(sm) + (r * PITCH + tq * 4) * 4;
    }

    // prologue: tiles 0,1,2 in flight (3 groups)
    #pragma unroll
    for (int p = 0; p < NBUF; p++) {
        #pragma unroll
        for (int q = 0; q < 4; q++) cp_async16(sbase[q] + p * TILE_BYTES, gbase[q] + p * TT);
        cp_commit();
    }

    // ---- scan state ----
    int   last = -1000000;                // chunk-local time of previous spike
    int   k = 0, ft = -1;
    int   curc = 0, curpc = 0;  float cursum = 0.0f;
    int   Fc = 0,   Fp = 0;     float Fs = 0.0f;
    int   Ic = SENT, Ip = 0;    float Is = 0.0f;

    const float* myrow0 = sm + tid * PITCH;
    int buf = 0;

    #pragma unroll 1
    for (int tile = 0; tile < NTILE; tile++) {
        // Drain exactly so this tile's group is complete (ladder at ring drain).
        if (tile < NTILE - 2)       cp_wait<2>();
        else if (tile == NTILE - 2) cp_wait<1>();
        else                        cp_wait<0>();
        __syncwarp();                     // producer lanes' smem writes visible warp-wide

        const float* r = myrow0 + buf * TILE_FLOATS;

        // 16-bit spike mask from sign bits: PRMT pack + magic multiply.
        uint32_t nm = 0;
        #pragma unroll
        for (int j = 0; j < 4; j++) {
            const uint4 u = *reinterpret_cast<const uint4*>(r + 4 * j);
            uint32_t t0 = __byte_perm(u.x, u.y, 0x0073);   // [x.b3, y.b3, ..]
            uint32_t t1 = __byte_perm(u.z, u.w, 0x0073);   // [z.b3, w.b3, ..]
            uint32_t sb = __byte_perm(t0, t1, 0x5410);     // [x3,y3,z3,w3]
            sb &= 0x80808080u;
            const uint32_t nib = (sb * 0x00204081u) >> 28; // bit0=x .. bit3=w (sign bits)
            nm |= nib << (4 * j);
        }
        uint32_t m = (~nm) & 0xFFFFu;     // spike mask (v >= 0)

        if (m) {
            const int wb = tile * TT;
            if (ft < 0) ft = wb + __ffs(m) - 1;
            do {
                const int i = __ffs(m) - 1;
                m &= m - 1;
                const float v = r[i];     // v >= 0 guaranteed
                const int  tg = wb + i;
                const bool nw = (tg - last) > C_GAP;
                const bool cF = nw && (k == 1);
                const bool cI = nw && (k >= 2) && (curc < Ic);
                Fc = cF ? curc : Fc;  Fs = cF ? cursum : Fs;  Fp = cF ? curpc : Fp;
                Ic = cI ? curc : Ic;  Is = cI ? cursum : Is;  Ip = cI ? curpc : Ip;
                k += nw;
                curc   = (nw ? 0 : curc) + 1;
                cursum = (nw ? 0.0f : cursum) + v;
                curpc  = (nw ? 0 : curpc) + (v > 0.0f ? 1 : 0);
                last = tg;
            } while (m);
        }

        __syncwarp();                     // all lanes done reading buf
        if (tile + NBUF < NTILE) {        // refill buf with tile+3
            const uint32_t soff = buf * TILE_BYTES;
            const int goff = (tile + NBUF) * TT;
            #pragma unroll
            for (int q = 0; q < 4; q++) cp_async16(sbase[q] + soff, gbase[q] + goff);
            cp_commit();
        }
        buf = (buf == NBUF - 1) ? 0 : buf + 1;
    }

    if (k == 1) { Fc = curc; Fs = cursum; Fp = curpc; }

    // Lazy vmax: only needed when the chunk has NO spikes (P ~ 4e-16). Rescan gmem.
    float vmax = -FLT_MAX;
    if (k == 0) {
        const float* g = vmem + (size_t)(traceBase + (tid & 31)) * T_DIM + c * CHUNK_T;
        #pragma unroll 1
        for (int j = 0; j < CHUNK_T; j++) vmax = fmaxf(vmax, g[j]);
    }

    // ---- chunk summaries to smem: [128][16] (single block barrier first) ----
    __syncthreads();
    float* summ = sm;
    {
        float* w = summ + tid * 16;
        w[0]  = vmax;
        w[1]  = (float)(ft < 0 ? -1 : c * CHUNK_T + ft);
        w[2]  = (float)(c * CHUNK_T + last);
        w[3]  = (float)k;
        w[4]  = (float)Fc;   w[5]  = Fs;     w[6]  = (float)Fp;
        w[7]  = (float)Ic;   w[8]  = Is;     w[9]  = (float)Ip;
        w[10] = (float)curc; w[11] = cursum; w[12] = (float)curpc;
    }
    __syncthreads();

    // ---- merge 4 chunk summaries per trace (threads 0..31) ----
    float* red = sm + TPB * 16;
    float contrib = 0.0f;
    if (tid < TR_PB) {
        float vx = -FLT_MAX;
        int last_t = -1000000, nclust = 0;
        int   opc = -1, opp = 0;  float ops = 0.0f;            // open cluster
        int   bc = SENT, bp = 0;  float bs = 0.0f;             // best closed
        #pragma unroll
        for (int cc = 0; cc < S_CHUNKS; cc++) {
            const float* w = summ + (cc * TR_PB + tid) * 16;
            vx = fmaxf(vx, w[0]);
            const int kk = (int)w[3];
            if (kk == 0) continue;
            const int ftc = (int)w[1], ltc = (int)w[2];
            const int fC = (int)w[4], fP = (int)w[6];
            const int iC = (int)w[7], iP = (int)w[9];
            const int lC = (int)w[10], lP = (int)w[12];
            const float fS = w[5], iS = w[8], lS = w[11];

            if (opc >= 0 && (ftc - last_t) <= C_GAP) {
                const int   mc = opc + fC;
                const float ms = ops + fS;
                const int   mp = opp + fP;
                if (kk == 1) { opc = mc; ops = ms; opp = mp; }
                else {
                    if (mc < bc) { bc = mc; bs = ms; bp = mp; }
                    if (iC < bc) { bc = iC; bs = iS; bp = iP; }
                    opc = lC; ops = lS; opp = lP;
                    nclust += kk - 1;
                }
            } else {
                if (opc >= 0 && opc < bc) { bc = opc; bs = ops; bp = opp; }
                nclust += kk;
                if (kk == 1) { opc = fC; ops = fS; opp = fP; }
                else {
                    if (fC < bc) { bc = fC; bs = fS; bp = fP; }
                    if (iC < bc) { bc = iC; bs = iS; bp = iP; }
                    opc = lC; ops = lS; opp = lP;
                }
            }
            last_t = ltc;
        }
        if (opc >= 0 && opc < bc) { bc = opc; bs = ops; bp = opp; }

        const int trace = traceBase + tid;
        out[1 + trace] = (float)nclust;

        const int b = trace / N_DIM;
        const int n = trace - b * N_DIM;
        if (n == labels[b]) {
            if (nclust == 0) contrib = -vx;
        } else if (nclust > 0) {
            contrib = bs / fmaxf((float)bp, 1.0f);
        }
    }

    // ---- block tree reduction (128 threads; >=32 contribute 0) ----
    red[tid] = contrib;
    __syncthreads();
    #pragma unroll
    for (int off = TPB / 2; off > 0; off >>= 1) {
        if (tid < off) red[tid] += red[tid + off];
        __syncthreads();
    }
    if (tid == 0) {
        g_partial[blockIdx.x] = red[0];
        __threadfence();
        amLast = (atomicAdd(&g_count, 1u) == (unsigned)(gridDim.x - 1));
    }
    __syncthreads();

    if (amLast) {
        __threadfence();
        float x = 0.0f;
        #pragma unroll
        for (int j = 0; j < NBLOCKS / TPB; j++) x += g_partial[tid + TPB * j];
        red[tid] = x;
        __syncthreads();
        #pragma unroll
        for (int off = TPB / 2; off > 0; off >>= 1) {
            if (tid < off) red[tid] += red[tid + off];
            __syncthreads();
        }
        if (tid == 0) {
            out[0] = red[0];
            g_count = 0;                  // reset for next graph replay
        }
    }
}

extern "C" void kernel_launch(void* const* d_in, const int* in_sizes, int n_in,
                              void* d_out, int out_size)
{
    const float* vmem   = (const float*)d_in[0];
    // d_in[1] (vlastmem) unused by the forward computation.
    const int*   labels = (const int*)d_in[2];
    float*       out    = (float*)d_out;

    stca_fused<<<NBLOCKS, TPB>>>(vmem, labels, out);
}